// round 15
// baseline (speedup 1.0000x reference)
#include <cuda_runtime.h>
#include <cuda_bf16.h>
#include <math.h>
#include <stdint.h>

// ---------------- static config ----------------
#define Bq   4
#define Cq   96
#define SSz  4
#define NHq  3
#define MLPH 384
#define TOKENS (Bq*256*256)

#define SCALEq 0.17677669529663687f
#define EPSq   1e-5f

// ---------------- precomputed tables ----------------
static __device__ __align__(16) __nv_bfloat16 g_cbias[4 * 3 * 64 * 64];  // (bias+mask)[pattern][head]
static __device__ __align__(16) uint4 g_qkvf[3 * 1152];
static __device__ __align__(16) uint4 g_projf[1152];
static __device__ __align__(16) uint4 g_fc1f[3 * 1536];
static __device__ __align__(16) uint4 g_fc2f[3 * 1536];

// ---------------- warp-mma helpers ----------------
__device__ __forceinline__ uint32_t smem_u32(const void* p) {
    uint32_t a;
    asm("{ .reg .u64 t; cvta.to.shared.u64 t, %1; cvt.u32.u64 %0, t; }" : "=r"(a) : "l"(p));
    return a;
}
__device__ __forceinline__ void ldm4(uint32_t* r, uint32_t addr) {
    asm volatile("ldmatrix.sync.aligned.m8n8.x4.shared.b16 {%0,%1,%2,%3}, [%4];"
        : "=r"(r[0]), "=r"(r[1]), "=r"(r[2]), "=r"(r[3]) : "r"(addr));
}
__device__ __forceinline__ void stm4(uint32_t addr, uint32_t r0, uint32_t r1, uint32_t r2, uint32_t r3) {
    asm volatile("stmatrix.sync.aligned.m8n8.x4.shared.b16 [%0], {%1,%2,%3,%4};"
        :: "r"(addr), "r"(r0), "r"(r1), "r"(r2), "r"(r3));
}
__device__ __forceinline__ void stm4t(uint32_t addr, uint32_t r0, uint32_t r1, uint32_t r2, uint32_t r3) {
    asm volatile("stmatrix.sync.aligned.m8n8.x4.trans.shared.b16 [%0], {%1,%2,%3,%4};"
        :: "r"(addr), "r"(r0), "r"(r1), "r"(r2), "r"(r3));
}
__device__ __forceinline__ void mma_bf16(float* c, const uint32_t* a, const uint32_t* b) {
    asm volatile("mma.sync.aligned.m16n8k16.row.col.f32.bf16.bf16.f32 "
        "{%0,%1,%2,%3}, {%4,%5,%6,%7}, {%8,%9}, {%0,%1,%2,%3};"
        : "+f"(c[0]), "+f"(c[1]), "+f"(c[2]), "+f"(c[3])
        : "r"(a[0]), "r"(a[1]), "r"(a[2]), "r"(a[3]), "r"(b[0]), "r"(b[1]));
}
__device__ __forceinline__ float gelu_f(float v) {
    float t;
    const float u = 0.7978845608028654f * fmaf(0.044715f * v * v, v, v);
    asm("tanh.approx.f32 %0, %1;" : "=f"(t) : "f"(u));
    const float hv = 0.5f * v;
    return fmaf(hv, t, hv);
}
__device__ __forceinline__ uint32_t packbf(float a, float b) {
    const __nv_bfloat162 h = __floats2bfloat162_rn(a, b);
    return *(const uint32_t*)&h;
}
__device__ __forceinline__ float2 unpackbf(uint32_t u) {
    const __nv_bfloat162 h = *(const __nv_bfloat162*)&u;
    return make_float2(__bfloat162float(h.x), __bfloat162float(h.y));
}

// ================= prep =================
__device__ __forceinline__ uint4 make_frag(const float* W, int ld, int rowoff, int coloff,
                                           int nt2, int kt, int lane) {
    uint32_t f[4];
    #pragma unroll
    for (int j = 0; j < 4; j++) {
        const int row = rowoff + nt2 * 16 + (lane >> 2) + ((j >= 2) ? 8 : 0);
        const int col = coloff + kt * 16 + ((j & 1) ? 8 : 0) + (lane & 3) * 2;
        f[j] = packbf(W[row * ld + col], W[row * ld + col + 1]);
    }
    return make_uint4(f[0], f[1], f[2], f[3]);
}

__global__ void prep_kernel(const float* __restrict__ rpb, const int* __restrict__ rel_index,
                            const float* __restrict__ attn_mask,
                            const float* __restrict__ qkv_w, const float* __restrict__ proj_w,
                            const float* __restrict__ fc1_w, const float* __restrict__ fc2_w)
{
    const int idx = blockIdx.x * 256 + threadIdx.x;   // 192*256 = 49152
    // combined bias+mask: 4 patterns x 3 heads x 4096
    if (idx < 49152) {
        const int p = idx / 12288, r = idx % 12288;
        const int hh = r >> 12, ij = r & 4095;
        const int wsel = (p == 0) ? 0 : (p == 1) ? 31 : (p == 2) ? 992 : 1023;
        g_cbias[idx] = __float2bfloat16(rpb[rel_index[ij] * 3 + hh]
                                        + attn_mask[(size_t)wsel * 4096 + ij]);
    }
    if (idx < 3456) {
        const int c = idx / 1152, r = idx % 1152;
        const int lane = r & 31, t = r >> 5, kt = t % 6, nt2 = t / 6;
        g_qkvf[idx] = make_frag(qkv_w, 96, c * 96, 0, nt2, kt, lane);
    } else if (idx < 4608) {
        const int r = idx - 3456;
        const int lane = r & 31, t = r >> 5, kt = t % 6, nt2 = t / 6;
        g_projf[r] = make_frag(proj_w, 96, 0, 0, nt2, kt, lane);
    } else if (idx < 9216) {
        const int r = idx - 4608, c = r / 1536, rr = r % 1536;
        const int lane = rr & 31, t = rr >> 5, kt = t % 6, nt2 = t / 6;
        g_fc1f[r] = make_frag(fc1_w, 96, c * 128, 0, nt2, kt, lane);
    } else if (idx < 13824) {
        const int r = idx - 9216, c = r / 1536, rr = r % 1536;
        const int lane = rr & 31, t = rr >> 5, kt = t % 8, nt2 = t / 8;
        g_fc2f[r] = make_frag(fc2_w, 384, 0, c * 128, nt2, kt, lane);
    }
}

// ---------------- fused smem layout (bytes) ----------------
// A  [0,26624):      LN1 -> Q -> O -> LN2'd A -> x2 scratch cols 48..95
// K  [26624,53248):  K -> x2 scratch cols 0..47
// VT [53248,88064):  v^T [96][136] -> H [128][136]
#define SAT 104
#define SVT 136
#define AS_A  0
#define AS_K  26624
#define AS_VT 53248
#define AS_TOTAL 88064

// ================= fused block kernel: 2 windows (128 tokens) per CTA =========
__global__ __launch_bounds__(256, 2)
void swin_block_fused(const float* __restrict__ x,
                      const float* __restrict__ g1, const float* __restrict__ b1,
                      const float* __restrict__ qkv_b, const float* __restrict__ proj_b,
                      const float* __restrict__ g2, const float* __restrict__ b2,
                      const float* __restrict__ fc1_b, const float* __restrict__ fc2_b,
                      float* __restrict__ out)
{
    extern __shared__ __align__(16) char smem[];
    const uint32_t sb = smem_u32(smem);
    const int tid = threadIdx.x, lane = tid & 31, warp = tid >> 5;

    const int wglob = blockIdx.x * 2 + (warp >> 2);
    const int b     = wglob >> 10;
    const int wrem  = wglob & 1023;
    const int wy    = wrem >> 5, wx = wrem & 31;
    const int wl    = warp >> 2;
    const int mrow0 = warp * 16;
    const int wm = warp & 3, wn = warp >> 2;
    const int m32r = wm * 32;

    // ---- LN1 + gather -> A bf16 (own 16 rows) ----
    #pragma unroll
    for (int r = 0; r < 16; r++) {
        const int t = mrow0 + r;
        const int i = t & 63;
        const int yy = (wy * 8 + (i >> 3) + SSz) & 255;
        const int xx = (wx * 8 + (i & 7) + SSz) & 255;
        const float* row = x + (size_t)(b * 65536 + yy * 256 + xx) * Cq;
        float v0 = row[lane], v1 = row[lane + 32], v2 = row[lane + 64];
        float s  = v0 + v1 + v2;
        float ss = v0 * v0 + v1 * v1 + v2 * v2;
        #pragma unroll
        for (int o = 16; o; o >>= 1) {
            s  += __shfl_xor_sync(0xffffffffu, s,  o);
            ss += __shfl_xor_sync(0xffffffffu, ss, o);
        }
        const float mu  = s * (1.0f / 96.0f);
        const float var = ss * (1.0f / 96.0f) - mu * mu;
        const float inv = rsqrtf(var + EPSq);
        __nv_bfloat16* arow = (__nv_bfloat16*)(smem + AS_A) + t * SAT;
        arow[lane]      = __float2bfloat16((v0 - mu) * inv * g1[lane]      + b1[lane]);
        arow[lane + 32] = __float2bfloat16((v1 - mu) * inv * g1[lane + 32] + b1[lane + 32]);
        arow[lane + 64] = __float2bfloat16((v2 - mu) * inv * g1[lane + 64] + b1[lane + 64]);
    }
    __syncthreads();   // bar: LN1 rows visible (afr reads span 2 warps' rows)

    // ---- A fragments for m32 strip ----
    uint32_t afr[2][6][4];
    #pragma unroll
    for (int mt = 0; mt < 2; mt++)
        #pragma unroll
        for (int k = 0; k < 6; k++)
            ldm4(afr[mt][k], sb + AS_A + (uint32_t)(((m32r + mt * 16 + (lane & 15)) * SAT
                                                    + k * 16 + ((lane >> 4) << 3)) * 2));
    __syncthreads();   // bar: all afr captured before Q overwrites A

    const int g = lane >> 2, tq = lane & 3;

    // ---- stmatrix per-lane base addresses ----
    const int st_r = lane & 7, st_sel = lane >> 3;
    const uint32_t st_row  = st_r + ((st_sel & 1) << 3);
    const uint32_t st_colb = (uint32_t)((st_sel & 2) << 3);
    const uint32_t stA = sb + AS_A + (mrow0 + st_row) * 208 + st_colb;        // m16 (attention O, LN2)
    // m32 QKV stores: col base wn*48
    const uint32_t stA32 = sb + AS_A + (m32r + st_row) * 208 + st_colb + (uint32_t)(wn * 96);
    const uint32_t stK32 = sb + AS_K + (m32r + st_row) * 208 + st_colb + (uint32_t)(wn * 96);
    // V^T trans store: row base = wn*48 (channel), col = token
    const uint32_t stVT32 = sb + AS_VT + (st_r + ((st_sel & 2) << 2) + wn * 48) * 272
                          + ((uint32_t)(st_sel & 1) << 4)
                          + (uint32_t)((m32r >> 6) * 64 + (m32r & 63)) * 2;

    // ---- QKV m32 x n-split: Q -> A, K -> K, V^T -> VT ----
    #pragma unroll
    for (int nt2 = 0; nt2 < 3; nt2++) {
        float q[2][8], kk[2][8], v[2][8];
        #pragma unroll
        for (int mt = 0; mt < 2; mt++)
            #pragma unroll
            for (int j = 0; j < 8; j++) { q[mt][j] = 0.f; kk[mt][j] = 0.f; v[mt][j] = 0.f; }
        #pragma unroll
        for (int kt = 0; kt < 6; kt++) {
            const int fi = ((wn * 3 + nt2) * 6 + kt) * 32 + lane;
            uint4 fq = g_qkvf[fi];
            uint4 fk = g_qkvf[1152 + fi];
            uint4 fv = g_qkvf[2304 + fi];
            #pragma unroll
            for (int mt = 0; mt < 2; mt++) {
                mma_bf16(q[mt],      afr[mt][kt], &fq.x);
                mma_bf16(q[mt] + 4,  afr[mt][kt], &fq.z);
                mma_bf16(kk[mt],     afr[mt][kt], &fk.x);
                mma_bf16(kk[mt] + 4, afr[mt][kt], &fk.z);
                mma_bf16(v[mt],      afr[mt][kt], &fv.x);
                mma_bf16(v[mt] + 4,  afr[mt][kt], &fv.z);
            }
        }
        const int n = wn * 48 + nt2 * 16 + 2 * tq;
        const float qb0 = qkv_b[n],       qb1 = qkv_b[n + 1];
        const float qb8 = qkv_b[n + 8],   qb9 = qkv_b[n + 9];
        const float kb0 = qkv_b[96 + n],  kb1 = qkv_b[96 + n + 1];
        const float kb8 = qkv_b[96 + n + 8], kb9 = qkv_b[96 + n + 9];
        const float vb0 = qkv_b[192 + n], vb1 = qkv_b[192 + n + 1];
        const float vb8 = qkv_b[192 + n + 8], vb9 = qkv_b[192 + n + 9];
        #pragma unroll
        for (int mt = 0; mt < 2; mt++) {
            stm4(stA32 + mt * (16 * 208) + nt2 * 32,
                 packbf((q[mt][0] + qb0) * SCALEq, (q[mt][1] + qb1) * SCALEq),
                 packbf((q[mt][2] + qb0) * SCALEq, (q[mt][3] + qb1) * SCALEq),
                 packbf((q[mt][4] + qb8) * SCALEq, (q[mt][5] + qb9) * SCALEq),
                 packbf((q[mt][6] + qb8) * SCALEq, (q[mt][7] + qb9) * SCALEq));
            stm4(stK32 + mt * (16 * 208) + nt2 * 32,
                 packbf(kk[mt][0] + kb0, kk[mt][1] + kb1),
                 packbf(kk[mt][2] + kb0, kk[mt][3] + kb1),
                 packbf(kk[mt][4] + kb8, kk[mt][5] + kb9),
                 packbf(kk[mt][6] + kb8, kk[mt][7] + kb9));
            stm4t(stVT32 + (uint32_t)(nt2 * 16) * 272 + mt * 32,
                  packbf(v[mt][0] + vb0, v[mt][1] + vb1),
                  packbf(v[mt][2] + vb0, v[mt][3] + vb1),
                  packbf(v[mt][4] + vb8, v[mt][5] + vb9),
                  packbf(v[mt][6] + vb8, v[mt][7] + vb9));
        }
    }
    __syncthreads();   // bar: Q + K + V^T visible

    // ---- per-head attention (Q from A region, combined bias+mask table) ----
    const int i0 = (warp & 3) * 16;
    const int pat = ((wy == 31) ? 2 : 0) | ((wx == 31) ? 1 : 0);
    for (int hh = 0; hh < NHq; hh++) {
        float sc[4][8];
        uint32_t qa[2][4];
        #pragma unroll
        for (int kt2 = 0; kt2 < 2; kt2++)
            ldm4(qa[kt2], sb + AS_A + (uint32_t)(((mrow0 + (lane & 15)) * SAT
                                                 + hh * 32 + kt2 * 16 + ((lane >> 4) << 3)) * 2));
        #pragma unroll
        for (int nt2 = 0; nt2 < 4; nt2++) {
            #pragma unroll
            for (int q = 0; q < 8; q++) sc[nt2][q] = 0.f;
            #pragma unroll
            for (int kt2 = 0; kt2 < 2; kt2++) {
                uint32_t bfr[4];
                ldm4(bfr, sb + AS_K + (uint32_t)(((wl * 64 + nt2 * 16 + (lane & 7) + ((lane & 16) ? 8 : 0)) * SAT
                                                 + hh * 32 + kt2 * 16 + ((lane & 8) ? 8 : 0)) * 2));
                mma_bf16(sc[nt2],     qa[kt2], bfr);
                mma_bf16(sc[nt2] + 4, qa[kt2], bfr + 2);
            }
        }
        const __nv_bfloat16* bias_h = g_cbias + (pat * 3 + hh) * 4096;
        #pragma unroll
        for (int nt2 = 0; nt2 < 4; nt2++)
            #pragma unroll
            for (int t2 = 0; t2 < 2; t2++) {
                const int col = nt2 * 16 + t2 * 8 + 2 * tq;
                #pragma unroll
                for (int rs = 0; rs < 2; rs++) {
                    float* cp = &sc[nt2][t2 * 4 + rs * 2];
                    const float2 f = unpackbf(*(const uint32_t*)(bias_h + (i0 + g + rs * 8) * 64 + col));
                    cp[0] += f.x;
                    cp[1] += f.y;
                }
            }
        float mx0 = -1e30f, mx1 = -1e30f;
        #pragma unroll
        for (int nt2 = 0; nt2 < 4; nt2++)
            #pragma unroll
            for (int t2 = 0; t2 < 2; t2++) {
                mx0 = fmaxf(mx0, fmaxf(sc[nt2][t2 * 4],     sc[nt2][t2 * 4 + 1]));
                mx1 = fmaxf(mx1, fmaxf(sc[nt2][t2 * 4 + 2], sc[nt2][t2 * 4 + 3]));
            }
        mx0 = fmaxf(mx0, __shfl_xor_sync(0xffffffffu, mx0, 1));
        mx0 = fmaxf(mx0, __shfl_xor_sync(0xffffffffu, mx0, 2));
        mx1 = fmaxf(mx1, __shfl_xor_sync(0xffffffffu, mx1, 1));
        mx1 = fmaxf(mx1, __shfl_xor_sync(0xffffffffu, mx1, 2));
        float s0 = 0.f, s1 = 0.f;
        #pragma unroll
        for (int nt2 = 0; nt2 < 4; nt2++)
            #pragma unroll
            for (int t2 = 0; t2 < 2; t2++) {
                float* cp = &sc[nt2][t2 * 4];
                cp[0] = __expf(cp[0] - mx0); cp[1] = __expf(cp[1] - mx0);
                cp[2] = __expf(cp[2] - mx1); cp[3] = __expf(cp[3] - mx1);
                s0 += cp[0] + cp[1];
                s1 += cp[2] + cp[3];
            }
        s0 += __shfl_xor_sync(0xffffffffu, s0, 1);
        s0 += __shfl_xor_sync(0xffffffffu, s0, 2);
        s1 += __shfl_xor_sync(0xffffffffu, s1, 1);
        s1 += __shfl_xor_sync(0xffffffffu, s1, 2);
        const float inv0 = 1.0f / s0, inv1 = 1.0f / s1;
        uint32_t pa[4][4];
        #pragma unroll
        for (int kt = 0; kt < 4; kt++) {
            pa[kt][0] = packbf(sc[kt][0] * inv0, sc[kt][1] * inv0);
            pa[kt][1] = packbf(sc[kt][2] * inv1, sc[kt][3] * inv1);
            pa[kt][2] = packbf(sc[kt][4] * inv0, sc[kt][5] * inv0);
            pa[kt][3] = packbf(sc[kt][6] * inv1, sc[kt][7] * inv1);
        }
        #pragma unroll
        for (int nb = 0; nb < 2; nb++) {
            float oc0[4] = {0.f,0.f,0.f,0.f}, oc1[4] = {0.f,0.f,0.f,0.f};
            #pragma unroll
            for (int kt = 0; kt < 4; kt++) {
                uint32_t bfr[4];
                ldm4(bfr, sb + AS_VT + (uint32_t)(((hh * 32 + nb * 16 + (lane & 7) + ((lane & 16) ? 8 : 0)) * SVT
                                                  + wl * 64 + kt * 16 + ((lane & 8) ? 8 : 0)) * 2));
                mma_bf16(oc0, pa[kt], bfr);
                mma_bf16(oc1, pa[kt], bfr + 2);
            }
            stm4(stA + (uint32_t)(hh * 32 + nb * 16) * 2,
                 packbf(oc0[0], oc0[1]), packbf(oc0[2], oc0[3]),
                 packbf(oc1[0], oc1[1]), packbf(oc1[2], oc1[3]));
        }
    }
    __syncthreads();   // bar: K/V^T reads done; O visible

    // ---- residual base addresses (m16) ----
    size_t baseA, baseB;
    {
        const int tA = mrow0 + g, tB = tA + 8;
        const int iA = tA & 63, iB = tB & 63;
        const int yyA = (wy * 8 + (iA >> 3) + SSz) & 255, xxA = (wx * 8 + (iA & 7) + SSz) & 255;
        const int yyB = (wy * 8 + (iB >> 3) + SSz) & 255, xxB = (wx * 8 + (iB & 7) + SSz) & 255;
        baseA = ((size_t)(b * 65536 + yyA * 256 + xxA)) * Cq;
        baseB = ((size_t)(b * 65536 + yyB * 256 + xxB)) * Cq;
    }

    // ---- proj mma + LN2 (m16); x2 -> fp32 smem scratch ----
    float x2v[6][2][4];
    {
        uint32_t ofr2[6][4];
        #pragma unroll
        for (int k = 0; k < 6; k++)
            ldm4(ofr2[k], sb + AS_A + (uint32_t)(((mrow0 + (lane & 15)) * SAT + k * 16 + ((lane >> 4) << 3)) * 2));

        #pragma unroll
        for (int nt2 = 0; nt2 < 6; nt2++) {
            float c0[4] = {0.f,0.f,0.f,0.f}, c1[4] = {0.f,0.f,0.f,0.f};
            #pragma unroll
            for (int kt = 0; kt < 6; kt++) {
                uint4 f = g_projf[(nt2 * 6 + kt) * 32 + lane];
                mma_bf16(c0, ofr2[kt], &f.x);
                mma_bf16(c1, ofr2[kt], &f.z);
            }
            const int n = nt2 * 16 + 2 * tq;
            {
                const float b0 = proj_b[n], b1v = proj_b[n + 1];
                const float2 xA = *(const float2*)(x + baseA + n);
                const float2 xB = *(const float2*)(x + baseB + n);
                x2v[nt2][0][0] = xA.x + c0[0] + b0;  x2v[nt2][0][1] = xA.y + c0[1] + b1v;
                x2v[nt2][0][2] = xB.x + c0[2] + b0;  x2v[nt2][0][3] = xB.y + c0[3] + b1v;
            }
            {
                const float b0 = proj_b[n + 8], b1v = proj_b[n + 9];
                const float2 xA = *(const float2*)(x + baseA + n + 8);
                const float2 xB = *(const float2*)(x + baseB + n + 8);
                x2v[nt2][1][0] = xA.x + c1[0] + b0;  x2v[nt2][1][1] = xA.y + c1[1] + b1v;
                x2v[nt2][1][2] = xB.x + c1[2] + b0;  x2v[nt2][1][3] = xB.y + c1[3] + b1v;
            }
        }

        float s0 = 0.f, ss0 = 0.f, s1 = 0.f, ss1 = 0.f;
        #pragma unroll
        for (int nt2 = 0; nt2 < 6; nt2++)
            #pragma unroll
            for (int tl = 0; tl < 2; tl++) {
                const float a0 = x2v[nt2][tl][0], a1 = x2v[nt2][tl][1];
                const float a2 = x2v[nt2][tl][2], a3 = x2v[nt2][tl][3];
                s0 += a0 + a1;  ss0 += a0 * a0 + a1 * a1;
                s1 += a2 + a3;  ss1 += a2 * a2 + a3 * a3;
            }
        s0  += __shfl_xor_sync(0xffffffffu, s0, 1);  s0  += __shfl_xor_sync(0xffffffffu, s0, 2);
        ss0 += __shfl_xor_sync(0xffffffffu, ss0, 1); ss0 += __shfl_xor_sync(0xffffffffu, ss0, 2);
        s1  += __shfl_xor_sync(0xffffffffu, s1, 1);  s1  += __shfl_xor_sync(0xffffffffu, s1, 2);
        ss1 += __shfl_xor_sync(0xffffffffu, ss1, 1); ss1 += __shfl_xor_sync(0xffffffffu, ss1, 2);
        const float mu0 = s0 * (1.0f / 96.0f);
        const float iv0 = rsqrtf(ss0 * (1.0f / 96.0f) - mu0 * mu0 + EPSq);
        const float mu1 = s1 * (1.0f / 96.0f);
        const float iv1 = rsqrtf(ss1 * (1.0f / 96.0f) - mu1 * mu1 + EPSq);
        #pragma unroll
        for (int nt2 = 0; nt2 < 6; nt2++) {
            const int n = nt2 * 16 + 2 * tq;
            const float ga0 = g2[n], gb0 = g2[n + 1], ba0 = b2[n], bb0 = b2[n + 1];
            const float ga1 = g2[n + 8], gb1 = g2[n + 9], ba1 = b2[n + 8], bb1 = b2[n + 9];
            stm4(stA + nt2 * 32,
                 packbf((x2v[nt2][0][0] - mu0) * iv0 * ga0 + ba0,
                        (x2v[nt2][0][1] - mu0) * iv0 * gb0 + bb0),
                 packbf((x2v[nt2][0][2] - mu1) * iv1 * ga0 + ba0,
                        (x2v[nt2][0][3] - mu1) * iv1 * gb0 + bb0),
                 packbf((x2v[nt2][1][0] - mu0) * iv0 * ga1 + ba1,
                        (x2v[nt2][1][1] - mu0) * iv0 * gb1 + bb1),
                 packbf((x2v[nt2][1][2] - mu1) * iv1 * ga1 + ba1,
                        (x2v[nt2][1][3] - mu1) * iv1 * gb1 + bb1));
        }
        // x2 cols 0..47 -> K scratch (fp32, stride 52)
        #pragma unroll
        for (int nt2 = 0; nt2 < 3; nt2++)
            #pragma unroll
            for (int tl = 0; tl < 2; tl++) {
                const int n = nt2 * 16 + tl * 8 + 2 * tq;
                *(float2*)(smem + AS_K + ((mrow0 + g) * 52 + n) * 4) =
                    make_float2(x2v[nt2][tl][0], x2v[nt2][tl][1]);
                *(float2*)(smem + AS_K + ((mrow0 + g + 8) * 52 + n) * 4) =
                    make_float2(x2v[nt2][tl][2], x2v[nt2][tl][3]);
            }
    }
    __syncthreads();   // bar: LN2'd A + x2K visible

    // ---- mafr capture (m32) ----
    uint32_t mafr[2][6][4];
    #pragma unroll
    for (int mt = 0; mt < 2; mt++)
        #pragma unroll
        for (int k = 0; k < 6; k++)
            ldm4(mafr[mt][k], sb + AS_A + (uint32_t)(((m32r + mt * 16 + (lane & 15)) * SAT
                                                     + k * 16 + ((lane >> 4) << 3)) * 2));
    __syncthreads();   // bar: mafr done before A overwritten

    // x2 cols 48..95 -> A scratch (fp32, stride 52)
    #pragma unroll
    for (int nt2 = 3; nt2 < 6; nt2++)
        #pragma unroll
        for (int tl = 0; tl < 2; tl++) {
            const int n = nt2 * 16 + tl * 8 + 2 * tq;
            *(float2*)(smem + AS_A + ((mrow0 + g) * 52 + (n - 48)) * 4) =
                make_float2(x2v[nt2][tl][0], x2v[nt2][tl][1]);
            *(float2*)(smem + AS_A + ((mrow0 + g + 8) * 52 + (n - 48)) * 4) =
                make_float2(x2v[nt2][tl][2], x2v[nt2][tl][3]);
        }

    // ================= MLP m32 x n-split ==========
    const uint32_t stH32 = sb + AS_VT + (m32r + st_row) * 272 + st_colb + (uint32_t)(wn * 128);
    float ofr[3][2][8];
    #pragma unroll
    for (int i = 0; i < 3; i++)
        #pragma unroll
        for (int j = 0; j < 2; j++)
            #pragma unroll
            for (int q = 0; q < 8; q++) ofr[i][j][q] = 0.f;

    for (int chunk = 0; chunk < 3; chunk++) {
        #pragma unroll
        for (int nt2 = 0; nt2 < 4; nt2++) {
            float c[2][8];
            #pragma unroll
            for (int j = 0; j < 2; j++)
                #pragma unroll
                for (int q = 0; q < 8; q++) c[j][q] = 0.f;
            #pragma unroll
            for (int k = 0; k < 6; k++) {
                uint4 f = g_fc1f[chunk * 1536 + ((wn * 4 + nt2) * 6 + k) * 32 + lane];
                mma_bf16(c[0],     mafr[0][k], &f.x);
                mma_bf16(c[0] + 4, mafr[0][k], &f.z);
                mma_bf16(c[1],     mafr[1][k], &f.x);
                mma_bf16(c[1] + 4, mafr[1][k], &f.z);
            }
            const int nn = chunk * 128 + wn * 64 + nt2 * 16 + 2 * tq;
            const float bb0 = fc1_b[nn],     bb1 = fc1_b[nn + 1];
            const float bb8 = fc1_b[nn + 8], bb9 = fc1_b[nn + 9];
            #pragma unroll
            for (int mt = 0; mt < 2; mt++) {
                stm4(stH32 + mt * 4352 + nt2 * 32,
                     packbf(gelu_f(c[mt][0] + bb0), gelu_f(c[mt][1] + bb1)),
                     packbf(gelu_f(c[mt][2] + bb0), gelu_f(c[mt][3] + bb1)),
                     packbf(gelu_f(c[mt][4] + bb8), gelu_f(c[mt][5] + bb9)),
                     packbf(gelu_f(c[mt][6] + bb8), gelu_f(c[mt][7] + bb9)));
            }
        }
        if (chunk == 0) __syncthreads();
        else asm volatile("bar.sync %0, 64;" :: "r"(wm + 1) : "memory");

        #pragma unroll
        for (int k = 0; k < 8; k++) {
            uint32_t hfr0[4], hfr1[4];
            ldm4(hfr0, sb + AS_VT + (uint32_t)(((m32r + (lane & 15)) * SVT + k * 16 + ((lane >> 4) << 3)) * 2));
            ldm4(hfr1, sb + AS_VT + (uint32_t)(((m32r + 16 + (lane & 15)) * SVT + k * 16 + ((lane >> 4) << 3)) * 2));
            #pragma unroll
            for (int nt2 = 0; nt2 < 3; nt2++) {
                uint4 f = g_fc2f[chunk * 1536 + ((wn * 3 + nt2) * 8 + k) * 32 + lane];
                mma_bf16(ofr[nt2][0],     hfr0, &f.x);
                mma_bf16(ofr[nt2][0] + 4, hfr0, &f.z);
                mma_bf16(ofr[nt2][1],     hfr1, &f.x);
                mma_bf16(ofr[nt2][1] + 4, hfr1, &f.z);
            }
        }
        if (chunk < 2)
            asm volatile("bar.sync %0, 64;" :: "r"(wm + 1) : "memory");
    }

    // ---- epilogue (m32): out = x2(smem) + ofr + fc2_b ----
    {
        const int wge = blockIdx.x * 2 + (wm >> 1);
        const int bre = wge >> 10, wre2 = wge & 1023;
        const int wye = wre2 >> 5, wxe = wre2 & 31;
        size_t eb[2][2];
        #pragma unroll
        for (int mt = 0; mt < 2; mt++)
            #pragma unroll
            for (int rs = 0; rs < 2; rs++) {
                const int t = m32r + mt * 16 + rs * 8 + g;
                const int i = t & 63;
                const int yy = (wye * 8 + (i >> 3) + SSz) & 255;
                const int xx = (wxe * 8 + (i & 7) + SSz) & 255;
                eb[mt][rs] = ((size_t)(bre * 65536 + yy * 256 + xx)) * Cq;
            }
        const uint32_t scrb = wn ? AS_A : AS_K;
        #pragma unroll
        for (int nt2 = 0; nt2 < 3; nt2++) {
            #pragma unroll
            for (int ntile = 0; ntile < 2; ntile++) {
                const int n = wn * 48 + nt2 * 16 + ntile * 8 + 2 * tq;
                const int colo = n - wn * 48;
                const float b0 = fc2_b[n], b1v = fc2_b[n + 1];
                #pragma unroll
                for (int mt = 0; mt < 2; mt++) {
                    const float* c = &ofr[nt2][mt][ntile * 4];
                    const int row0 = m32r + mt * 16 + g;
                    const float2 xa = *(const float2*)(smem + scrb + (row0 * 52 + colo) * 4);
                    const float2 xb = *(const float2*)(smem + scrb + ((row0 + 8) * 52 + colo) * 4);
                    *(float2*)(out + eb[mt][0] + n) = make_float2(xa.x + c[0] + b0, xa.y + c[1] + b1v);
                    *(float2*)(out + eb[mt][1] + n) = make_float2(xb.x + c[2] + b0, xb.y + c[3] + b1v);
                }
            }
        }
    }
}

// ================= launch =================
extern "C" void kernel_launch(void* const* d_in, const int* in_sizes, int n_in,
                              void* d_out, int out_size)
{
    const float* x        = (const float*)d_in[0];
    const float* g1       = (const float*)d_in[1];
    const float* b1       = (const float*)d_in[2];
    const float* qkv_w    = (const float*)d_in[3];
    const float* qkv_b    = (const float*)d_in[4];
    const float* rpb      = (const float*)d_in[5];
    const float* proj_w   = (const float*)d_in[6];
    const float* proj_b   = (const float*)d_in[7];
    const float* g2       = (const float*)d_in[8];
    const float* b2       = (const float*)d_in[9];
    const float* fc1_w    = (const float*)d_in[10];
    const float* fc1_b    = (const float*)d_in[11];
    const float* fc2_w    = (const float*)d_in[12];
    const float* fc2_b    = (const float*)d_in[13];
    const float* attn_mask= (const float*)d_in[14];
    const int*   rel_index= (const int*)  d_in[15];
    float* out = (float*)d_out;

    cudaFuncSetAttribute(swin_block_fused, cudaFuncAttributeMaxDynamicSharedMemorySize, AS_TOTAL);

    prep_kernel<<<192, 256>>>(rpb, rel_index, attn_mask, qkv_w, proj_w, fc1_w, fc2_w);
    swin_block_fused<<<TOKENS / 128, 256, AS_TOTAL>>>(x, g1, b1, qkv_b, proj_b,
                                                      g2, b2, fc1_b, fc2_b, out);
}

// round 16
// speedup vs baseline: 1.0717x; 1.0717x over previous
#include <cuda_runtime.h>
#include <cuda_bf16.h>
#include <math.h>
#include <stdint.h>

// ---------------- static config ----------------
#define Bq   4
#define Cq   96
#define SSz  4
#define NHq  3
#define MLPH 384
#define TOKENS (Bq*256*256)

#define SCALEq 0.17677669529663687f
#define EPSq   1e-5f

// ---------------- precomputed tables ----------------
static __device__ __align__(16) __nv_bfloat16 g_cbias[4 * 3 * 64 * 64];  // (bias+mask)[pattern][head]
static __device__ __align__(16) uint4 g_qkvf[3 * 1152];
static __device__ __align__(16) uint4 g_projf[1152];
static __device__ __align__(16) uint4 g_fc1f[3 * 1536];
static __device__ __align__(16) uint4 g_fc2f[3 * 1536];

// ---------------- warp-mma helpers ----------------
__device__ __forceinline__ uint32_t smem_u32(const void* p) {
    uint32_t a;
    asm("{ .reg .u64 t; cvta.to.shared.u64 t, %1; cvt.u32.u64 %0, t; }" : "=r"(a) : "l"(p));
    return a;
}
__device__ __forceinline__ void ldm4(uint32_t* r, uint32_t addr) {
    asm volatile("ldmatrix.sync.aligned.m8n8.x4.shared.b16 {%0,%1,%2,%3}, [%4];"
        : "=r"(r[0]), "=r"(r[1]), "=r"(r[2]), "=r"(r[3]) : "r"(addr));
}
__device__ __forceinline__ void stm4(uint32_t addr, uint32_t r0, uint32_t r1, uint32_t r2, uint32_t r3) {
    asm volatile("stmatrix.sync.aligned.m8n8.x4.shared.b16 [%0], {%1,%2,%3,%4};"
        :: "r"(addr), "r"(r0), "r"(r1), "r"(r2), "r"(r3));
}
__device__ __forceinline__ void stm4t(uint32_t addr, uint32_t r0, uint32_t r1, uint32_t r2, uint32_t r3) {
    asm volatile("stmatrix.sync.aligned.m8n8.x4.trans.shared.b16 [%0], {%1,%2,%3,%4};"
        :: "r"(addr), "r"(r0), "r"(r1), "r"(r2), "r"(r3));
}
__device__ __forceinline__ void mma_bf16(float* c, const uint32_t* a, const uint32_t* b) {
    asm volatile("mma.sync.aligned.m16n8k16.row.col.f32.bf16.bf16.f32 "
        "{%0,%1,%2,%3}, {%4,%5,%6,%7}, {%8,%9}, {%0,%1,%2,%3};"
        : "+f"(c[0]), "+f"(c[1]), "+f"(c[2]), "+f"(c[3])
        : "r"(a[0]), "r"(a[1]), "r"(a[2]), "r"(a[3]), "r"(b[0]), "r"(b[1]));
}
__device__ __forceinline__ float gelu_f(float v) {
    float t;
    const float u = 0.7978845608028654f * fmaf(0.044715f * v * v, v, v);
    asm("tanh.approx.f32 %0, %1;" : "=f"(t) : "f"(u));
    const float hv = 0.5f * v;
    return fmaf(hv, t, hv);
}
__device__ __forceinline__ uint32_t packbf(float a, float b) {
    const __nv_bfloat162 h = __floats2bfloat162_rn(a, b);
    return *(const uint32_t*)&h;
}
__device__ __forceinline__ float2 unpackbf(uint32_t u) {
    const __nv_bfloat162 h = *(const __nv_bfloat162*)&u;
    return make_float2(__bfloat162float(h.x), __bfloat162float(h.y));
}

// ================= prep =================
__device__ __forceinline__ uint4 make_frag(const float* W, int ld, int rowoff, int coloff,
                                           int nt2, int kt, int lane) {
    uint32_t f[4];
    #pragma unroll
    for (int j = 0; j < 4; j++) {
        const int row = rowoff + nt2 * 16 + (lane >> 2) + ((j >= 2) ? 8 : 0);
        const int col = coloff + kt * 16 + ((j & 1) ? 8 : 0) + (lane & 3) * 2;
        f[j] = packbf(W[row * ld + col], W[row * ld + col + 1]);
    }
    return make_uint4(f[0], f[1], f[2], f[3]);
}

__global__ void prep_kernel(const float* __restrict__ rpb, const int* __restrict__ rel_index,
                            const float* __restrict__ attn_mask,
                            const float* __restrict__ qkv_w, const float* __restrict__ proj_w,
                            const float* __restrict__ fc1_w, const float* __restrict__ fc2_w)
{
    const int idx = blockIdx.x * 256 + threadIdx.x;   // 192*256 = 49152
    if (idx < 49152) {
        const int p = idx / 12288, r = idx % 12288;
        const int hh = r >> 12, ij = r & 4095;
        const int wsel = (p == 0) ? 0 : (p == 1) ? 31 : (p == 2) ? 992 : 1023;
        g_cbias[idx] = __float2bfloat16(rpb[rel_index[ij] * 3 + hh]
                                        + attn_mask[(size_t)wsel * 4096 + ij]);
    }
    if (idx < 3456) {
        const int c = idx / 1152, r = idx % 1152;
        const int lane = r & 31, t = r >> 5, kt = t % 6, nt2 = t / 6;
        g_qkvf[idx] = make_frag(qkv_w, 96, c * 96, 0, nt2, kt, lane);
    } else if (idx < 4608) {
        const int r = idx - 3456;
        const int lane = r & 31, t = r >> 5, kt = t % 6, nt2 = t / 6;
        g_projf[r] = make_frag(proj_w, 96, 0, 0, nt2, kt, lane);
    } else if (idx < 9216) {
        const int r = idx - 4608, c = r / 1536, rr = r % 1536;
        const int lane = rr & 31, t = rr >> 5, kt = t % 6, nt2 = t / 6;
        g_fc1f[r] = make_frag(fc1_w, 96, c * 128, 0, nt2, kt, lane);
    } else if (idx < 13824) {
        const int r = idx - 9216, c = r / 1536, rr = r % 1536;
        const int lane = rr & 31, t = rr >> 5, kt = t % 8, nt2 = t / 8;
        g_fc2f[r] = make_frag(fc2_w, 384, 0, c * 128, nt2, kt, lane);
    }
}

// ---------------- fused smem layout (bytes) ----------------
// A  [0,26624):      LN1 -> O -> LN2'd A -> x2 scratch cols 48..95 (fp32 [128][52])
// K  [26624,53248):  K -> x2 scratch cols 0..47 (fp32 [128][52])
// VT [53248,88064):  v^T [96][136] -> H [128][136]
#define SAT 104
#define SVT 136
#define AS_A  0
#define AS_K  26624
#define AS_VT 53248
#define AS_TOTAL 88064

// ================= fused block kernel: 2 windows (128 tokens) per CTA =========
__global__ __launch_bounds__(256, 2)
void swin_block_fused(const float* __restrict__ x,
                      const float* __restrict__ g1, const float* __restrict__ b1,
                      const float* __restrict__ qkv_b, const float* __restrict__ proj_b,
                      const float* __restrict__ g2, const float* __restrict__ b2,
                      const float* __restrict__ fc1_b, const float* __restrict__ fc2_b,
                      float* __restrict__ out)
{
    extern __shared__ __align__(16) char smem[];
    const uint32_t sb = smem_u32(smem);
    const int tid = threadIdx.x, lane = tid & 31, warp = tid >> 5;

    const int wglob = blockIdx.x * 2 + (warp >> 2);
    const int b     = wglob >> 10;
    const int wrem  = wglob & 1023;
    const int wy    = wrem >> 5, wx = wrem & 31;
    const int wl    = warp >> 2;
    const int mrow0 = warp * 16;

    // ---- LN1 + gather -> A bf16 (own rows) ----
    #pragma unroll
    for (int r = 0; r < 16; r++) {
        const int t = mrow0 + r;
        const int i = t & 63;
        const int yy = (wy * 8 + (i >> 3) + SSz) & 255;
        const int xx = (wx * 8 + (i & 7) + SSz) & 255;
        const float* row = x + (size_t)(b * 65536 + yy * 256 + xx) * Cq;
        float v0 = row[lane], v1 = row[lane + 32], v2 = row[lane + 64];
        float s  = v0 + v1 + v2;
        float ss = v0 * v0 + v1 * v1 + v2 * v2;
        #pragma unroll
        for (int o = 16; o; o >>= 1) {
            s  += __shfl_xor_sync(0xffffffffu, s,  o);
            ss += __shfl_xor_sync(0xffffffffu, ss, o);
        }
        const float mu  = s * (1.0f / 96.0f);
        const float var = ss * (1.0f / 96.0f) - mu * mu;
        const float inv = rsqrtf(var + EPSq);
        __nv_bfloat16* arow = (__nv_bfloat16*)(smem + AS_A) + t * SAT;
        arow[lane]      = __float2bfloat16((v0 - mu) * inv * g1[lane]      + b1[lane]);
        arow[lane + 32] = __float2bfloat16((v1 - mu) * inv * g1[lane + 32] + b1[lane + 32]);
        arow[lane + 64] = __float2bfloat16((v2 - mu) * inv * g1[lane + 64] + b1[lane + 64]);
    }
    __syncwarp();

    // ---- A fragments (own rows) ----
    uint32_t afr[6][4];
    #pragma unroll
    for (int k = 0; k < 6; k++)
        ldm4(afr[k], sb + AS_A + (uint32_t)(((mrow0 + (lane & 15)) * SAT + k * 16 + ((lane >> 4) << 3)) * 2));

    const int g = lane >> 2, tq = lane & 3;

    // ---- stmatrix per-lane base addresses ----
    const int st_r = lane & 7, st_sel = lane >> 3;
    const uint32_t st_row  = st_r + ((st_sel & 1) << 3);
    const uint32_t st_colb = (uint32_t)((st_sel & 2) << 3);
    const uint32_t stA = sb + AS_A + (mrow0 + st_row) * 208 + st_colb;
    const uint32_t stK = sb + AS_K + (mrow0 + st_row) * 208 + st_colb;
    const uint32_t stVT = sb + AS_VT + (st_r + ((st_sel & 2) << 2)) * 272
                        + ((uint32_t)(st_sel & 1) << 4)
                        + (uint32_t)(wl * 64 + (warp & 3) * 16) * 2;

    // ---- QKV: Q -> regs, K -> smem, V^T -> smem ----
    uint32_t qafr[6][4];
    #pragma unroll
    for (int nt2 = 0; nt2 < 6; nt2++) {
        float c0[4] = {0.f,0.f,0.f,0.f}, c1[4] = {0.f,0.f,0.f,0.f};
        float d0[4] = {0.f,0.f,0.f,0.f}, d1[4] = {0.f,0.f,0.f,0.f};
        float e0[4] = {0.f,0.f,0.f,0.f}, e1[4] = {0.f,0.f,0.f,0.f};
        #pragma unroll
        for (int kt = 0; kt < 6; kt++) {
            const int fi = (nt2 * 6 + kt) * 32 + lane;
            uint4 fq = g_qkvf[fi];
            uint4 fk = g_qkvf[1152 + fi];
            uint4 fv = g_qkvf[2304 + fi];
            mma_bf16(c0, afr[kt], &fq.x);
            mma_bf16(c1, afr[kt], &fq.z);
            mma_bf16(d0, afr[kt], &fk.x);
            mma_bf16(d1, afr[kt], &fk.z);
            mma_bf16(e0, afr[kt], &fv.x);
            mma_bf16(e1, afr[kt], &fv.z);
        }
        const int n = nt2 * 16 + 2 * tq;
        {
            const float b0 = qkv_b[n],     b1v = qkv_b[n + 1];
            const float b8 = qkv_b[n + 8], b9  = qkv_b[n + 9];
            qafr[nt2][0] = packbf((c0[0] + b0) * SCALEq, (c0[1] + b1v) * SCALEq);
            qafr[nt2][1] = packbf((c0[2] + b0) * SCALEq, (c0[3] + b1v) * SCALEq);
            qafr[nt2][2] = packbf((c1[0] + b8) * SCALEq, (c1[1] + b9) * SCALEq);
            qafr[nt2][3] = packbf((c1[2] + b8) * SCALEq, (c1[3] + b9) * SCALEq);
        }
        {
            const float b0 = qkv_b[96 + n],     b1v = qkv_b[96 + n + 1];
            const float b8 = qkv_b[96 + n + 8], b9  = qkv_b[96 + n + 9];
            stm4(stK + nt2 * 32,
                 packbf(d0[0] + b0, d0[1] + b1v), packbf(d0[2] + b0, d0[3] + b1v),
                 packbf(d1[0] + b8, d1[1] + b9),  packbf(d1[2] + b8, d1[3] + b9));
        }
        {
            const float b0 = qkv_b[192 + n],     b1v = qkv_b[192 + n + 1];
            const float b8 = qkv_b[192 + n + 8], b9  = qkv_b[192 + n + 9];
            stm4t(stVT + (uint32_t)(nt2 * 16) * 272,
                  packbf(e0[0] + b0, e0[1] + b1v), packbf(e0[2] + b0, e0[3] + b1v),
                  packbf(e1[0] + b8, e1[1] + b9),  packbf(e1[2] + b8, e1[3] + b9));
        }
    }
    __syncthreads();   // bar#1: K + V^T visible

    // ---- per-head attention (combined bias+mask table) ----
    const int i0 = (warp & 3) * 16;
    const int pat = ((wy == 31) ? 2 : 0) | ((wx == 31) ? 1 : 0);
    for (int hh = 0; hh < NHq; hh++) {
        float sc[4][8];
        #pragma unroll
        for (int nt2 = 0; nt2 < 4; nt2++) {
            #pragma unroll
            for (int q = 0; q < 8; q++) sc[nt2][q] = 0.f;
            #pragma unroll
            for (int kt2 = 0; kt2 < 2; kt2++) {
                uint32_t bfr[4];
                ldm4(bfr, sb + AS_K + (uint32_t)(((wl * 64 + nt2 * 16 + (lane & 7) + ((lane & 16) ? 8 : 0)) * SAT
                                                 + hh * 32 + kt2 * 16 + ((lane & 8) ? 8 : 0)) * 2));
                mma_bf16(sc[nt2],     qafr[2 * hh + kt2], bfr);
                mma_bf16(sc[nt2] + 4, qafr[2 * hh + kt2], bfr + 2);
            }
        }
        const __nv_bfloat16* bias_h = g_cbias + (pat * 3 + hh) * 4096;
        #pragma unroll
        for (int nt2 = 0; nt2 < 4; nt2++)
            #pragma unroll
            for (int t2 = 0; t2 < 2; t2++) {
                const int col = nt2 * 16 + t2 * 8 + 2 * tq;
                #pragma unroll
                for (int rs = 0; rs < 2; rs++) {
                    float* cp = &sc[nt2][t2 * 4 + rs * 2];
                    const float2 f = unpackbf(*(const uint32_t*)(bias_h + (i0 + g + rs * 8) * 64 + col));
                    cp[0] += f.x;
                    cp[1] += f.y;
                }
            }
        float mx0 = -1e30f, mx1 = -1e30f;
        #pragma unroll
        for (int nt2 = 0; nt2 < 4; nt2++)
            #pragma unroll
            for (int t2 = 0; t2 < 2; t2++) {
                mx0 = fmaxf(mx0, fmaxf(sc[nt2][t2 * 4],     sc[nt2][t2 * 4 + 1]));
                mx1 = fmaxf(mx1, fmaxf(sc[nt2][t2 * 4 + 2], sc[nt2][t2 * 4 + 3]));
            }
        mx0 = fmaxf(mx0, __shfl_xor_sync(0xffffffffu, mx0, 1));
        mx0 = fmaxf(mx0, __shfl_xor_sync(0xffffffffu, mx0, 2));
        mx1 = fmaxf(mx1, __shfl_xor_sync(0xffffffffu, mx1, 1));
        mx1 = fmaxf(mx1, __shfl_xor_sync(0xffffffffu, mx1, 2));
        float s0 = 0.f, s1 = 0.f;
        #pragma unroll
        for (int nt2 = 0; nt2 < 4; nt2++)
            #pragma unroll
            for (int t2 = 0; t2 < 2; t2++) {
                float* cp = &sc[nt2][t2 * 4];
                cp[0] = __expf(cp[0] - mx0); cp[1] = __expf(cp[1] - mx0);
                cp[2] = __expf(cp[2] - mx1); cp[3] = __expf(cp[3] - mx1);
                s0 += cp[0] + cp[1];
                s1 += cp[2] + cp[3];
            }
        s0 += __shfl_xor_sync(0xffffffffu, s0, 1);
        s0 += __shfl_xor_sync(0xffffffffu, s0, 2);
        s1 += __shfl_xor_sync(0xffffffffu, s1, 1);
        s1 += __shfl_xor_sync(0xffffffffu, s1, 2);
        const float inv0 = 1.0f / s0, inv1 = 1.0f / s1;
        uint32_t pa[4][4];
        #pragma unroll
        for (int kt = 0; kt < 4; kt++) {
            pa[kt][0] = packbf(sc[kt][0] * inv0, sc[kt][1] * inv0);
            pa[kt][1] = packbf(sc[kt][2] * inv1, sc[kt][3] * inv1);
            pa[kt][2] = packbf(sc[kt][4] * inv0, sc[kt][5] * inv0);
            pa[kt][3] = packbf(sc[kt][6] * inv1, sc[kt][7] * inv1);
        }
        #pragma unroll
        for (int nb = 0; nb < 2; nb++) {
            float oc0[4] = {0.f,0.f,0.f,0.f}, oc1[4] = {0.f,0.f,0.f,0.f};
            #pragma unroll
            for (int kt = 0; kt < 4; kt++) {
                uint32_t bfr[4];
                ldm4(bfr, sb + AS_VT + (uint32_t)(((hh * 32 + nb * 16 + (lane & 7) + ((lane & 16) ? 8 : 0)) * SVT
                                                  + wl * 64 + kt * 16 + ((lane & 8) ? 8 : 0)) * 2));
                mma_bf16(oc0, pa[kt], bfr);
                mma_bf16(oc1, pa[kt], bfr + 2);
            }
            stm4(stA + (uint32_t)(hh * 32 + nb * 16) * 2,
                 packbf(oc0[0], oc0[1]), packbf(oc0[2], oc0[3]),
                 packbf(oc1[0], oc1[1]), packbf(oc1[2], oc1[3]));
        }
    }
    __syncthreads();   // bar#2: K/V^T reads done; O visible

    // ---- residual base addresses (m16) ----
    size_t baseA, baseB;
    {
        const int tA = mrow0 + g, tB = tA + 8;
        const int iA = tA & 63, iB = tB & 63;
        const int yyA = (wy * 8 + (iA >> 3) + SSz) & 255, xxA = (wx * 8 + (iA & 7) + SSz) & 255;
        const int yyB = (wy * 8 + (iB >> 3) + SSz) & 255, xxB = (wx * 8 + (iB & 7) + SSz) & 255;
        baseA = ((size_t)(b * 65536 + yyA * 256 + xxA)) * Cq;
        baseB = ((size_t)(b * 65536 + yyB * 256 + xxB)) * Cq;
    }

    // ---- proj mma + LN2 (m16); x2 -> fp32 smem scratch ----
    float x2v[6][2][4];
    {
        uint32_t ofr2[6][4];
        #pragma unroll
        for (int k = 0; k < 6; k++)
            ldm4(ofr2[k], sb + AS_A + (uint32_t)(((mrow0 + (lane & 15)) * SAT + k * 16 + ((lane >> 4) << 3)) * 2));

        #pragma unroll
        for (int nt2 = 0; nt2 < 6; nt2++) {
            float c0[4] = {0.f,0.f,0.f,0.f}, c1[4] = {0.f,0.f,0.f,0.f};
            #pragma unroll
            for (int kt = 0; kt < 6; kt++) {
                uint4 f = g_projf[(nt2 * 6 + kt) * 32 + lane];
                mma_bf16(c0, ofr2[kt], &f.x);
                mma_bf16(c1, ofr2[kt], &f.z);
            }
            const int n = nt2 * 16 + 2 * tq;
            {
                const float b0 = proj_b[n], b1v = proj_b[n + 1];
                const float2 xA = *(const float2*)(x + baseA + n);
                const float2 xB = *(const float2*)(x + baseB + n);
                x2v[nt2][0][0] = xA.x + c0[0] + b0;  x2v[nt2][0][1] = xA.y + c0[1] + b1v;
                x2v[nt2][0][2] = xB.x + c0[2] + b0;  x2v[nt2][0][3] = xB.y + c0[3] + b1v;
            }
            {
                const float b0 = proj_b[n + 8], b1v = proj_b[n + 9];
                const float2 xA = *(const float2*)(x + baseA + n + 8);
                const float2 xB = *(const float2*)(x + baseB + n + 8);
                x2v[nt2][1][0] = xA.x + c1[0] + b0;  x2v[nt2][1][1] = xA.y + c1[1] + b1v;
                x2v[nt2][1][2] = xB.x + c1[2] + b0;  x2v[nt2][1][3] = xB.y + c1[3] + b1v;
            }
        }

        float s0 = 0.f, ss0 = 0.f, s1 = 0.f, ss1 = 0.f;
        #pragma unroll
        for (int nt2 = 0; nt2 < 6; nt2++)
            #pragma unroll
            for (int tl = 0; tl < 2; tl++) {
                const float a0 = x2v[nt2][tl][0], a1 = x2v[nt2][tl][1];
                const float a2 = x2v[nt2][tl][2], a3 = x2v[nt2][tl][3];
                s0 += a0 + a1;  ss0 += a0 * a0 + a1 * a1;
                s1 += a2 + a3;  ss1 += a2 * a2 + a3 * a3;
            }
        s0  += __shfl_xor_sync(0xffffffffu, s0, 1);  s0  += __shfl_xor_sync(0xffffffffu, s0, 2);
        ss0 += __shfl_xor_sync(0xffffffffu, ss0, 1); ss0 += __shfl_xor_sync(0xffffffffu, ss0, 2);
        s1  += __shfl_xor_sync(0xffffffffu, s1, 1);  s1  += __shfl_xor_sync(0xffffffffu, s1, 2);
        ss1 += __shfl_xor_sync(0xffffffffu, ss1, 1); ss1 += __shfl_xor_sync(0xffffffffu, ss1, 2);
        const float mu0 = s0 * (1.0f / 96.0f);
        const float iv0 = rsqrtf(ss0 * (1.0f / 96.0f) - mu0 * mu0 + EPSq);
        const float mu1 = s1 * (1.0f / 96.0f);
        const float iv1 = rsqrtf(ss1 * (1.0f / 96.0f) - mu1 * mu1 + EPSq);
        #pragma unroll
        for (int nt2 = 0; nt2 < 6; nt2++) {
            const int n = nt2 * 16 + 2 * tq;
            const float ga0 = g2[n], gb0 = g2[n + 1], ba0 = b2[n], bb0 = b2[n + 1];
            const float ga1 = g2[n + 8], gb1 = g2[n + 9], ba1 = b2[n + 8], bb1 = b2[n + 9];
            stm4(stA + nt2 * 32,
                 packbf((x2v[nt2][0][0] - mu0) * iv0 * ga0 + ba0,
                        (x2v[nt2][0][1] - mu0) * iv0 * gb0 + bb0),
                 packbf((x2v[nt2][0][2] - mu1) * iv1 * ga0 + ba0,
                        (x2v[nt2][0][3] - mu1) * iv1 * gb0 + bb0),
                 packbf((x2v[nt2][1][0] - mu0) * iv0 * ga1 + ba1,
                        (x2v[nt2][1][1] - mu0) * iv0 * gb1 + bb1),
                 packbf((x2v[nt2][1][2] - mu1) * iv1 * ga1 + ba1,
                        (x2v[nt2][1][3] - mu1) * iv1 * gb1 + bb1));
        }
        // x2 cols 0..47 -> K scratch (fp32, stride 52 floats)
        #pragma unroll
        for (int nt2 = 0; nt2 < 3; nt2++)
            #pragma unroll
            for (int tl = 0; tl < 2; tl++) {
                const int n = nt2 * 16 + tl * 8 + 2 * tq;
                *(float2*)(smem + AS_K + ((mrow0 + g) * 52 + n) * 4) =
                    make_float2(x2v[nt2][tl][0], x2v[nt2][tl][1]);
                *(float2*)(smem + AS_K + ((mrow0 + g + 8) * 52 + n) * 4) =
                    make_float2(x2v[nt2][tl][2], x2v[nt2][tl][3]);
            }
    }
    __syncthreads();   // bar#3: LN2'd A + x2K visible

    // ---- m32 setup + mafr capture ----
    const int wm = warp & 3, wn = warp >> 2;
    const int m32r = wm * 32;
    uint32_t mafr[2][6][4];
    #pragma unroll
    for (int mt = 0; mt < 2; mt++)
        #pragma unroll
        for (int k = 0; k < 6; k++)
            ldm4(mafr[mt][k], sb + AS_A + (uint32_t)(((m32r + mt * 16 + (lane & 15)) * SAT
                                                     + k * 16 + ((lane >> 4) << 3)) * 2));
    __syncthreads();   // bar#4: all mafr loads done before A overwritten

    // x2 cols 48..95 -> A scratch (fp32, stride 52 floats)
    #pragma unroll
    for (int nt2 = 3; nt2 < 6; nt2++)
        #pragma unroll
        for (int tl = 0; tl < 2; tl++) {
            const int n = nt2 * 16 + tl * 8 + 2 * tq;
            *(float2*)(smem + AS_A + ((mrow0 + g) * 52 + (n - 48)) * 4) =
                make_float2(x2v[nt2][tl][0], x2v[nt2][tl][1]);
            *(float2*)(smem + AS_A + ((mrow0 + g + 8) * 52 + (n - 48)) * 4) =
                make_float2(x2v[nt2][tl][2], x2v[nt2][tl][3]);
        }

    // ================= MLP m32 x n-split ==========
    const uint32_t stH32 = sb + AS_VT + (m32r + st_row) * 272 + st_colb + (uint32_t)(wn * 128);
    float ofr[3][2][8];
    #pragma unroll
    for (int i = 0; i < 3; i++)
        #pragma unroll
        for (int j = 0; j < 2; j++)
            #pragma unroll
            for (int q = 0; q < 8; q++) ofr[i][j][q] = 0.f;

    for (int chunk = 0; chunk < 3; chunk++) {
        // FC1 + GELU -> H (rows m32r..+32, cols wn*64..+64)
        #pragma unroll
        for (int nt2 = 0; nt2 < 4; nt2++) {
            float c[2][8];
            #pragma unroll
            for (int j = 0; j < 2; j++)
                #pragma unroll
                for (int q = 0; q < 8; q++) c[j][q] = 0.f;
            #pragma unroll
            for (int k = 0; k < 6; k++) {
                uint4 f = g_fc1f[chunk * 1536 + ((wn * 4 + nt2) * 6 + k) * 32 + lane];
                mma_bf16(c[0],     mafr[0][k], &f.x);
                mma_bf16(c[0] + 4, mafr[0][k], &f.z);
                mma_bf16(c[1],     mafr[1][k], &f.x);
                mma_bf16(c[1] + 4, mafr[1][k], &f.z);
            }
            const int nn = chunk * 128 + wn * 64 + nt2 * 16 + 2 * tq;
            const float bb0 = fc1_b[nn],     bb1 = fc1_b[nn + 1];
            const float bb8 = fc1_b[nn + 8], bb9 = fc1_b[nn + 9];
            #pragma unroll
            for (int mt = 0; mt < 2; mt++) {
                stm4(stH32 + mt * 4352 + nt2 * 32,
                     packbf(gelu_f(c[mt][0] + bb0), gelu_f(c[mt][1] + bb1)),
                     packbf(gelu_f(c[mt][2] + bb0), gelu_f(c[mt][3] + bb1)),
                     packbf(gelu_f(c[mt][4] + bb8), gelu_f(c[mt][5] + bb9)),
                     packbf(gelu_f(c[mt][6] + bb8), gelu_f(c[mt][7] + bb9)));
            }
        }
        if (chunk == 0) __syncthreads();                          // also covers x2A visibility
        else asm volatile("bar.sync %0, 64;" :: "r"(wm + 1) : "memory");

        // FC2 accumulate (rows m32r..+32, cols wn*48..+48)
        #pragma unroll
        for (int k = 0; k < 8; k++) {
            uint32_t hfr0[4], hfr1[4];
            ldm4(hfr0, sb + AS_VT + (uint32_t)(((m32r + (lane & 15)) * SVT + k * 16 + ((lane >> 4) << 3)) * 2));
            ldm4(hfr1, sb + AS_VT + (uint32_t)(((m32r + 16 + (lane & 15)) * SVT + k * 16 + ((lane >> 4) << 3)) * 2));
            #pragma unroll
            for (int nt2 = 0; nt2 < 3; nt2++) {
                uint4 f = g_fc2f[chunk * 1536 + ((wn * 3 + nt2) * 8 + k) * 32 + lane];
                mma_bf16(ofr[nt2][0],     hfr0, &f.x);
                mma_bf16(ofr[nt2][0] + 4, hfr0, &f.z);
                mma_bf16(ofr[nt2][1],     hfr1, &f.x);
                mma_bf16(ofr[nt2][1] + 4, hfr1, &f.z);
            }
        }
        if (chunk < 2)
            asm volatile("bar.sync %0, 64;" :: "r"(wm + 1) : "memory");
    }

    // ---- epilogue (m32): out = x2(smem) + ofr + fc2_b ----
    {
        const int wge = blockIdx.x * 2 + (wm >> 1);
        const int bre = wge >> 10, wre2 = wge & 1023;
        const int wye = wre2 >> 5, wxe = wre2 & 31;
        size_t eb[2][2];
        #pragma unroll
        for (int mt = 0; mt < 2; mt++)
            #pragma unroll
            for (int rs = 0; rs < 2; rs++) {
                const int t = m32r + mt * 16 + rs * 8 + g;
                const int i = t & 63;
                const int yy = (wye * 8 + (i >> 3) + SSz) & 255;
                const int xx = (wxe * 8 + (i & 7) + SSz) & 255;
                eb[mt][rs] = ((size_t)(bre * 65536 + yy * 256 + xx)) * Cq;
            }
        const uint32_t scrb = wn ? AS_A : AS_K;
        #pragma unroll
        for (int nt2 = 0; nt2 < 3; nt2++) {
            #pragma unroll
            for (int ntile = 0; ntile < 2; ntile++) {
                const int n = wn * 48 + nt2 * 16 + ntile * 8 + 2 * tq;
                const int colo = n - wn * 48;
                const float b0 = fc2_b[n], b1v = fc2_b[n + 1];
                #pragma unroll
                for (int mt = 0; mt < 2; mt++) {
                    const float* c = &ofr[nt2][mt][ntile * 4];
                    const int row0 = m32r + mt * 16 + g;
                    const float2 xa = *(const float2*)(smem + scrb + (row0 * 52 + colo) * 4);
                    const float2 xb = *(const float2*)(smem + scrb + ((row0 + 8) * 52 + colo) * 4);
                    *(float2*)(out + eb[mt][0] + n) = make_float2(xa.x + c[0] + b0, xa.y + c[1] + b1v);
                    *(float2*)(out + eb[mt][1] + n) = make_float2(xb.x + c[2] + b0, xb.y + c[3] + b1v);
                }
            }
        }
    }
}

// ================= launch =================
extern "C" void kernel_launch(void* const* d_in, const int* in_sizes, int n_in,
                              void* d_out, int out_size)
{
    const float* x        = (const float*)d_in[0];
    const float* g1       = (const float*)d_in[1];
    const float* b1       = (const float*)d_in[2];
    const float* qkv_w    = (const float*)d_in[3];
    const float* qkv_b    = (const float*)d_in[4];
    const float* rpb      = (const float*)d_in[5];
    const float* proj_w   = (const float*)d_in[6];
    const float* proj_b   = (const float*)d_in[7];
    const float* g2       = (const float*)d_in[8];
    const float* b2       = (const float*)d_in[9];
    const float* fc1_w    = (const float*)d_in[10];
    const float* fc1_b    = (const float*)d_in[11];
    const float* fc2_w    = (const float*)d_in[12];
    const float* fc2_b    = (const float*)d_in[13];
    const float* attn_mask= (const float*)d_in[14];
    const int*   rel_index= (const int*)  d_in[15];
    float* out = (float*)d_out;

    cudaFuncSetAttribute(swin_block_fused, cudaFuncAttributeMaxDynamicSharedMemorySize, AS_TOTAL);

    prep_kernel<<<192, 256>>>(rpb, rel_index, attn_mask, qkv_w, proj_w, fc1_w, fc2_w);
    swin_block_fused<<<TOKENS / 128, 256, AS_TOTAL>>>(x, g1, b1, qkv_b, proj_b,
                                                      g2, b2, fc1_b, fc2_b, out);
}